// round 15
// baseline (speedup 1.0000x reference)
#include <cuda_runtime.h>
#include <cstdint>
#include <math.h>

// ---------------- problem constants ----------------
#define NROWS   65536
#define SDIM    256
#define ADIM    129
#define HID     256
#define NSTEP   30
#define EPS_LN  1e-5f

#define TM      128     // rows per CTA (4 warps x 32)
#define WROWS   32
#define HS      260     // h smem stride (260%32=4 -> conflict-free scalar A reads)
#define XS      140     // x smem stride (140%32=12 -> conflict-free)
#define NTP     16      // B pairs per kt in 256-wide frag layouts
#define NTP3    9       // pairs per kt for W3 (144 cols)
#define KT      32      // k-tiles for K=256
#define KT1     17      // k-tiles for K=136

typedef unsigned int u32;

__device__ __forceinline__ u32 cvt_tf32(float x) {
    u32 r; asm("cvt.rna.tf32.f32 %0, %1;" : "=r"(r) : "f"(x)); return r;
}
__device__ __forceinline__ void mma8(float* c, const u32 a[4], u32 b0, u32 b1) {
    asm("mma.sync.aligned.m16n8k8.row.col.f32.tf32.tf32.f32 "
        "{%0,%1,%2,%3},{%4,%5,%6,%7},{%8,%9},{%0,%1,%2,%3};"
        : "+f"(c[0]), "+f"(c[1]), "+f"(c[2]), "+f"(c[3])
        : "r"(a[0]), "r"(a[1]), "r"(a[2]), "r"(a[3]), "r"(b0), "r"(b1));
}
__device__ __forceinline__ void split4(const float a[4], u32 ah[4], u32 al[4]) {
    #pragma unroll
    for (int j = 0; j < 4; j++) {
        ah[j] = cvt_tf32(a[j]);
        al[j] = cvt_tf32(a[j] - __uint_as_float(ah[j]));
    }
}

// ---------------- weight fragment streams (hi/lo tf32 split) ----------------
__device__ float g_W1s_hi[KT  * NTP  * 32 * 4];
__device__ float g_W1s_lo[KT  * NTP  * 32 * 4];
__device__ float g_W1x_hi[KT1 * NTP  * 32 * 4];
__device__ float g_W1x_lo[KT1 * NTP  * 32 * 4];
__device__ float g_W2_hi [KT  * NTP  * 32 * 4];
__device__ float g_W2_lo [KT  * NTP  * 32 * 4];
__device__ float g_W3_hi [KT  * NTP3 * 32 * 4];
__device__ float g_W3_lo [KT  * NTP3 * 32 * 4];
__device__ float g_b3p[144];
// per-warp S1 fragments (64 regs x 2 passes x 64 floats... = 8192 floats/warp)
__device__ float g_S1f[(size_t)(NROWS / WROWS) * 8192];
// per-warp raw C half0 scratch for L2 (32x128)
__device__ float g_scr[(size_t)(NROWS / WROWS) * 4096];

// one fragment slot (validK/validN guard, hi/lo split)
__device__ __forceinline__ void pack_region(const float* __restrict__ src,
                                            float* hi, float* lo, int stride,
                                            int validK, int validN, int ntpn,
                                            int kOff, int idx)
{
    int lane = idx & 31, rest = idx >> 5;
    int p = rest % ntpn, kt = rest / ntpn;
    int q = lane & 3, tq = lane >> 2;
    int k0 = kt * 8 + q, k1 = k0 + 4;
    int c0 = (2 * p) * 8 + tq, c1 = (2 * p + 1) * 8 + tq;
    float v[4];
    v[0] = (k0 < validK && c0 < validN) ? src[(size_t)(k0 + kOff) * stride + c0] : 0.0f;
    v[1] = (k1 < validK && c0 < validN) ? src[(size_t)(k1 + kOff) * stride + c0] : 0.0f;
    v[2] = (k0 < validK && c1 < validN) ? src[(size_t)(k0 + kOff) * stride + c1] : 0.0f;
    v[3] = (k1 < validK && c1 < validN) ? src[(size_t)(k1 + kOff) * stride + c1] : 0.0f;
    float4 Hv, Lv;
    u32 h;
    h = cvt_tf32(v[0]); Hv.x = __uint_as_float(h); Lv.x = __uint_as_float(cvt_tf32(v[0] - __uint_as_float(h)));
    h = cvt_tf32(v[1]); Hv.y = __uint_as_float(h); Lv.y = __uint_as_float(cvt_tf32(v[1] - __uint_as_float(h)));
    h = cvt_tf32(v[2]); Hv.z = __uint_as_float(h); Lv.z = __uint_as_float(cvt_tf32(v[2] - __uint_as_float(h)));
    h = cvt_tf32(v[3]); Hv.w = __uint_as_float(h); Lv.w = __uint_as_float(cvt_tf32(v[3] - __uint_as_float(h)));
    ((float4*)hi)[idx] = Hv;
    ((float4*)lo)[idx] = Lv;
}

// ONE pack kernel (so ncu -s 5 lands on actor_kernel)
#define R0 (KT  * NTP  * 32)   // 16384
#define R1 (R0 + KT1 * NTP * 32)
#define R2 (R1 + KT  * NTP * 32)
#define R3 (R2 + KT  * NTP3 * 32)  // 50688 total
__global__ void pack_all(const float* __restrict__ W1, const float* __restrict__ W2,
                         const float* __restrict__ W3, const float* __restrict__ b3)
{
    int i = blockIdx.x * 256 + threadIdx.x;
    if (i < 144) g_b3p[i] = (i < ADIM) ? b3[i] : 0.0f;
    if (i < R0)      pack_region(W1, g_W1s_hi, g_W1s_lo, HID, 256, 256, NTP, 0, i);
    else if (i < R1) pack_region(W1, g_W1x_hi, g_W1x_lo, HID, 129, 256, NTP, SDIM, i - R0);
    else if (i < R2) pack_region(W2, g_W2_hi,  g_W2_lo,  HID, 256, 256, NTP, 0, i - R1);
    else if (i < R3) pack_region(W3, g_W3_hi,  g_W3_lo,  ADIM, 256, 129, NTP3, 0, i - R2);
}

// ---------------- GEMM: 2 m16 tiles (32 rows), NPAIRS n-pairs, 3xTF32 ----------------
template<int KTN, int NPAIRS>
__device__ __forceinline__ void gemm2(float* cfr0, float* cfr1,
                                      const float* __restrict__ A, int astr,
                                      const float* __restrict__ Bh,
                                      const float* __restrict__ Bl,
                                      int ldp, int pOff, int lane)
{
    const int q = lane & 3, tq = lane >> 2;
    #pragma unroll 1
    for (int kt = 0; kt < KTN; kt++) {
        const int k0 = kt * 8 + q;
        float a0[4], a1[4];
        a0[0] = A[tq * astr + k0];        a0[1] = A[(tq + 8) * astr + k0];
        a0[2] = A[tq * astr + k0 + 4];    a0[3] = A[(tq + 8) * astr + k0 + 4];
        a1[0] = A[(tq + 16) * astr + k0];     a1[1] = A[(tq + 24) * astr + k0];
        a1[2] = A[(tq + 16) * astr + k0 + 4]; a1[3] = A[(tq + 24) * astr + k0 + 4];
        u32 ah0[4], al0[4], ah1[4], al1[4];
        split4(a0, ah0, al0);
        split4(a1, ah1, al1);
        const float4* bh = (const float4*)Bh + ((size_t)kt * ldp + pOff) * 32 + lane;
        const float4* bl = (const float4*)Bl + ((size_t)kt * ldp + pOff) * 32 + lane;
        #pragma unroll
        for (int p = 0; p < NPAIRS; p++) {
            const float4 h4 = bh[p * 32];
            const float4 l4 = bl[p * 32];
            const u32 h0 = __float_as_uint(h4.x), h1 = __float_as_uint(h4.y);
            const u32 h2 = __float_as_uint(h4.z), h3 = __float_as_uint(h4.w);
            const u32 l0 = __float_as_uint(l4.x), l1 = __float_as_uint(l4.y);
            const u32 l2 = __float_as_uint(l4.z), l3 = __float_as_uint(l4.w);
            float* c0 = cfr0 + p * 8;
            float* c1 = cfr1 + p * 8;
            mma8(c0,     ah0, h0, h1); mma8(c0,     ah0, l0, l1); mma8(c0,     al0, h0, h1);
            mma8(c0 + 4, ah0, h2, h3); mma8(c0 + 4, ah0, l2, l3); mma8(c0 + 4, al0, h2, h3);
            mma8(c1,     ah1, h0, h1); mma8(c1,     ah1, l0, l1); mma8(c1,     al1, h0, h1);
            mma8(c1 + 4, ah1, h2, h3); mma8(c1 + 4, ah1, l2, l3); mma8(c1 + 4, al1, h2, h3);
        }
    }
}

// C frag index map per pair p: [0,1]=row tq cols 2q,2q+1 | [2,3]=row tq+8 |
// [4..7] same rows, cols +8. cfr1 = rows +16.

__device__ __forceinline__ void init_bias2(float* cfr0, float* cfr1,
                                           const float* __restrict__ bias,
                                           int colbase, int npairs, int q)
{
    for (int p = 0; p < npairs; p++) {
        const float2 ba = *(const float2*)(bias + colbase + p * 16 + 2 * q);
        const float2 bb = *(const float2*)(bias + colbase + p * 16 + 8 + 2 * q);
        float* c0 = cfr0 + p * 8;
        float* c1 = cfr1 + p * 8;
        c0[0] = ba.x; c0[1] = ba.y; c0[2] = ba.x; c0[3] = ba.y;
        c0[4] = bb.x; c0[5] = bb.y; c0[6] = bb.x; c0[7] = bb.y;
        c1[0] = ba.x; c1[1] = ba.y; c1[2] = ba.x; c1[3] = ba.y;
        c1[4] = bb.x; c1[5] = bb.y; c1[6] = bb.x; c1[7] = bb.y;
    }
}

__device__ __forceinline__ void accum_stats(const float* cfr0, const float* cfr1,
                                            float S[4], float S2[4])
{
    #pragma unroll
    for (int p = 0; p < 8; p++) {
        const float* a = cfr0 + p * 8;
        const float* b = cfr1 + p * 8;
        S[0]  += a[0] + a[1] + a[4] + a[5];
        S2[0] += a[0]*a[0] + a[1]*a[1] + a[4]*a[4] + a[5]*a[5];
        S[1]  += a[2] + a[3] + a[6] + a[7];
        S2[1] += a[2]*a[2] + a[3]*a[3] + a[6]*a[6] + a[7]*a[7];
        S[2]  += b[0] + b[1] + b[4] + b[5];
        S2[2] += b[0]*b[0] + b[1]*b[1] + b[4]*b[4] + b[5]*b[5];
        S[3]  += b[2] + b[3] + b[6] + b[7];
        S2[3] += b[2]*b[2] + b[3]*b[3] + b[6]*b[6] + b[7]*b[7];
    }
}

// store raw C half (cols 0..127) to base (row stride rs)
__device__ __forceinline__ void store_raw(const float* cfr0, const float* cfr1,
                                          float* base, int rs, int q, int tq)
{
    #pragma unroll
    for (int p = 0; p < 8; p++) {
        const float* a = cfr0 + p * 8;
        const float* b = cfr1 + p * 8;
        const int c = p * 16 + 2 * q;
        float2 v;
        v.x = a[0]; v.y = a[1]; *(float2*)(base + tq * rs + c) = v;
        v.x = a[2]; v.y = a[3]; *(float2*)(base + (tq + 8) * rs + c) = v;
        v.x = b[0]; v.y = b[1]; *(float2*)(base + (tq + 16) * rs + c) = v;
        v.x = b[2]; v.y = b[3]; *(float2*)(base + (tq + 24) * rs + c) = v;
        v.x = a[4]; v.y = a[5]; *(float2*)(base + tq * rs + c + 8) = v;
        v.x = a[6]; v.y = a[7]; *(float2*)(base + (tq + 8) * rs + c + 8) = v;
        v.x = b[4]; v.y = b[5]; *(float2*)(base + (tq + 16) * rs + c + 8) = v;
        v.x = b[6]; v.y = b[7]; *(float2*)(base + (tq + 24) * rs + c + 8) = v;
    }
}

// normalize C half in regs -> hw at colbase
__device__ __forceinline__ void norm_reg(const float* cfr0, const float* cfr1,
                                         float* __restrict__ hw, int colbase,
                                         const float* __restrict__ g,
                                         const float* __restrict__ be,
                                         const float m[4], const float inv[4],
                                         int q, int tq)
{
    #pragma unroll
    for (int p = 0; p < 8; p++) {
        const float* a = cfr0 + p * 8;
        const float* b = cfr1 + p * 8;
        #pragma unroll
        for (int h = 0; h < 2; h++) {
            const int c = colbase + p * 16 + 8 * h + 2 * q;
            const float2 gg = *(const float2*)(g + c);
            const float2 bb = *(const float2*)(be + c);
            float2 v;
            v.x = fmaxf(fmaf((a[4*h+0] - m[0]) * inv[0], gg.x, bb.x), 0.0f);
            v.y = fmaxf(fmaf((a[4*h+1] - m[0]) * inv[0], gg.y, bb.y), 0.0f);
            *(float2*)(hw + tq * HS + c) = v;
            v.x = fmaxf(fmaf((a[4*h+2] - m[1]) * inv[1], gg.x, bb.x), 0.0f);
            v.y = fmaxf(fmaf((a[4*h+3] - m[1]) * inv[1], gg.y, bb.y), 0.0f);
            *(float2*)(hw + (tq + 8) * HS + c) = v;
            v.x = fmaxf(fmaf((b[4*h+0] - m[2]) * inv[2], gg.x, bb.x), 0.0f);
            v.y = fmaxf(fmaf((b[4*h+1] - m[2]) * inv[2], gg.y, bb.y), 0.0f);
            *(float2*)(hw + (tq + 16) * HS + c) = v;
            v.x = fmaxf(fmaf((b[4*h+2] - m[3]) * inv[3], gg.x, bb.x), 0.0f);
            v.y = fmaxf(fmaf((b[4*h+3] - m[3]) * inv[3], gg.y, bb.y), 0.0f);
            *(float2*)(hw + (tq + 24) * HS + c) = v;
        }
    }
}

// normalize raw half0 (cols 0..127) from mem -> hw
__device__ __forceinline__ void norm_mem(const float* __restrict__ raw, int rs,
                                         float* __restrict__ hw,
                                         const float* __restrict__ g,
                                         const float* __restrict__ be,
                                         const float m[4], const float inv[4],
                                         int q, int tq)
{
    #pragma unroll
    for (int p = 0; p < 16; p++) {     // 16 n-tiles = cols 0..127
        const int c = p * 8 + 2 * q;
        const float2 gg = *(const float2*)(g + c);
        const float2 bb = *(const float2*)(be + c);
        #pragma unroll
        for (int r = 0; r < 4; r++) {
            const int row = tq + 8 * r;
            const float2 rv = *(const float2*)(raw + row * rs + c);
            float2 v;
            v.x = fmaxf(fmaf((rv.x - m[r]) * inv[r], gg.x, bb.x), 0.0f);
            v.y = fmaxf(fmaf((rv.y - m[r]) * inv[r], gg.y, bb.y), 0.0f);
            *(float2*)(hw + row * HS + c) = v;
        }
    }
}

#define CBF   (8 * 256)
#define HBF   (TM * HS)
#define XBF   (TM * XS)
#define SMEM_BYTES ((CBF + HBF + XBF) * sizeof(float))   // 212992 B -> 1 CTA/SM

__global__ void __launch_bounds__(128, 1)
actor_kernel(const float* __restrict__ state,  const float* __restrict__ amask,
             const float* __restrict__ x_init, const float* __restrict__ gumbel,
             const float* __restrict__ W1,     const float* __restrict__ b1,
             const float* __restrict__ g1,     const float* __restrict__ be1,
             const float* __restrict__ W2,     const float* __restrict__ b2,
             const float* __restrict__ g2,     const float* __restrict__ be2,
             const float* __restrict__ b3,     float* __restrict__ out)
{
    extern __shared__ float sm[];
    float* cb = sm;               // [8][256]: g1,be1,g2,be2,b2,b3p,w385,b1
    float* hb = sm + CBF;         // [128][260]
    float* xb = sm + CBF + HBF;   // [128][140]

    const int tid  = threadIdx.x;
    const int lane = tid & 31;
    const int wid  = tid >> 5;
    const int q    = lane & 3, tq = lane >> 2;
    const int wr   = wid * WROWS;
    const size_t grow0 = (size_t)blockIdx.x * TM;
    float* hw = hb + wr * HS;
    float* xw = xb + wr * XS;
    const int warpgid = blockIdx.x * 4 + wid;
    float* s1p  = g_S1f + (size_t)warpgid * 8192;
    float* scrw = g_scr + (size_t)warpgid * 4096;

    // ---- stage constants ----
    for (int i = tid; i < 256; i += 128) {
        cb[0 * 256 + i] = g1[i];
        cb[1 * 256 + i] = be1[i];
        cb[2 * 256 + i] = g2[i];
        cb[3 * 256 + i] = be2[i];
        cb[4 * 256 + i] = b2[i];
        cb[5 * 256 + i] = (i < 144) ? g_b3p[i] : 0.0f;
        cb[6 * 256 + i] = W1[(size_t)385 * HID + i];
        cb[7 * 256 + i] = b1[i];
    }
    __syncthreads();

    // ---- stage x rows + state rows (warp-private 32 rows) ----
    #pragma unroll 1
    for (int i = 0; i < WROWS; i++) {
        const size_t gr = grow0 + wr + i;
        const float* xp = x_init + gr * ADIM;
        #pragma unroll
        for (int j = 0; j < 4; j++) xw[i * XS + lane + 32 * j] = xp[lane + 32 * j];
        if (lane == 0) xw[i * XS + 128] = xp[128];
        if (lane >= 1 && lane <= 11) xw[i * XS + 128 + lane] = 0.0f;
        const float* sp = state + gr * SDIM;
        *(float4*)(hw + i * HS + lane * 4)       = *(const float4*)(sp + lane * 4);
        *(float4*)(hw + i * HS + 128 + lane * 4) = *(const float4*)(sp + 128 + lane * 4);
    }
    __syncwarp();

    float cfr0[64], cfr1[64];

    // ---- S1 = state @ W1s + b1 -> g_S1f (two N-half passes) ----
    #pragma unroll 1
    for (int ph = 0; ph < 2; ph++) {
        init_bias2(cfr0, cfr1, cb + 7 * 256, ph * 128, 8, q);
        gemm2<KT, 8>(cfr0, cfr1, hw, HS, g_W1s_hi, g_W1s_lo, NTP, ph * 8, lane);
        #pragma unroll
        for (int p = 0; p < 8; p++) {
            float4 v;
            v.x = cfr0[p*8+0]; v.y = cfr0[p*8+1]; v.z = cfr0[p*8+2]; v.w = cfr0[p*8+3];
            *(float4*)(s1p + (((ph * 2 + 0) * 8 + p) * 2 + 0) * 128 + lane * 4) = v;
            v.x = cfr0[p*8+4]; v.y = cfr0[p*8+5]; v.z = cfr0[p*8+6]; v.w = cfr0[p*8+7];
            *(float4*)(s1p + (((ph * 2 + 0) * 8 + p) * 2 + 1) * 128 + lane * 4) = v;
            v.x = cfr1[p*8+0]; v.y = cfr1[p*8+1]; v.z = cfr1[p*8+2]; v.w = cfr1[p*8+3];
            *(float4*)(s1p + (((ph * 2 + 1) * 8 + p) * 2 + 0) * 128 + lane * 4) = v;
            v.x = cfr1[p*8+4]; v.y = cfr1[p*8+5]; v.z = cfr1[p*8+6]; v.w = cfr1[p*8+7];
            *(float4*)(s1p + (((ph * 2 + 1) * 8 + p) * 2 + 1) * 128 + lane * 4) = v;
        }
    }
    __syncwarp();

    // ---- 30 diffusion steps (warps fully independent) ----
    #pragma unroll 1
    for (int s = 0; s < NSTEP; s++) {
        const float t = (float)(NSTEP - 1 - s);
        float S[4], S2[4], m[4], inv[4];

        // ===== L1: C = S1 + t*w385; += x @ W1x; LN+ReLU -> h =====
        S[0]=S[1]=S[2]=S[3]=0.0f; S2[0]=S2[1]=S2[2]=S2[3]=0.0f;
        #pragma unroll 1
        for (int ph = 0; ph < 2; ph++) {
            // init from S1 blob + t*w385
            #pragma unroll
            for (int p = 0; p < 8; p++) {
                const int c = ph * 128 + p * 16 + 2 * q;
                const float2 wa = *(const float2*)(cb + 6 * 256 + c);
                const float2 wb = *(const float2*)(cb + 6 * 256 + c + 8);
                float4 v;
                v = *(float4*)(s1p + (((ph*2+0)*8+p)*2+0)*128 + lane*4);
                cfr0[p*8+0] = fmaf(t, wa.x, v.x); cfr0[p*8+1] = fmaf(t, wa.y, v.y);
                cfr0[p*8+2] = fmaf(t, wa.x, v.z); cfr0[p*8+3] = fmaf(t, wa.y, v.w);
                v = *(float4*)(s1p + (((ph*2+0)*8+p)*2+1)*128 + lane*4);
                cfr0[p*8+4] = fmaf(t, wb.x, v.x); cfr0[p*8+5] = fmaf(t, wb.y, v.y);
                cfr0[p*8+6] = fmaf(t, wb.x, v.z); cfr0[p*8+7] = fmaf(t, wb.y, v.w);
                v = *(float4*)(s1p + (((ph*2+1)*8+p)*2+0)*128 + lane*4);
                cfr1[p*8+0] = fmaf(t, wa.x, v.x); cfr1[p*8+1] = fmaf(t, wa.y, v.y);
                cfr1[p*8+2] = fmaf(t, wa.x, v.z); cfr1[p*8+3] = fmaf(t, wa.y, v.w);
                v = *(float4*)(s1p + (((ph*2+1)*8+p)*2+1)*128 + lane*4);
                cfr1[p*8+4] = fmaf(t, wb.x, v.x); cfr1[p*8+5] = fmaf(t, wb.y, v.y);
                cfr1[p*8+6] = fmaf(t, wb.x, v.z); cfr1[p*8+7] = fmaf(t, wb.y, v.w);
            }
            gemm2<KT1, 8>(cfr0, cfr1, xw, XS, g_W1x_hi, g_W1x_lo, NTP, ph * 8, lane);
            accum_stats(cfr0, cfr1, S, S2);
            if (ph == 0) store_raw(cfr0, cfr1, hw, HS, q, tq);   // h region free
        }
        #pragma unroll
        for (int r = 0; r < 4; r++) {
            S[r]  += __shfl_xor_sync(0xffffffffu, S[r], 1);
            S[r]  += __shfl_xor_sync(0xffffffffu, S[r], 2);
            S2[r] += __shfl_xor_sync(0xffffffffu, S2[r], 1);
            S2[r] += __shfl_xor_sync(0xffffffffu, S2[r], 2);
            m[r] = S[r] * (1.0f / 256.0f);
            inv[r] = rsqrtf(S2[r] * (1.0f / 256.0f) - m[r] * m[r] + EPS_LN);
        }
        norm_reg(cfr0, cfr1, hw, 128, cb + 0*256, cb + 1*256, m, inv, q, tq);
        norm_mem(hw, HS, hw, cb + 0*256, cb + 1*256, m, inv, q, tq);   // in-place
        __syncwarp();

        // ===== L2: C = b2; += h @ W2; LN+ReLU -> h (raw half0 via g_scr) =====
        S[0]=S[1]=S[2]=S[3]=0.0f; S2[0]=S2[1]=S2[2]=S2[3]=0.0f;
        #pragma unroll 1
        for (int ph = 0; ph < 2; ph++) {
            init_bias2(cfr0, cfr1, cb + 4 * 256, ph * 128, 8, q);
            gemm2<KT, 8>(cfr0, cfr1, hw, HS, g_W2_hi, g_W2_lo, NTP, ph * 8, lane);
            accum_stats(cfr0, cfr1, S, S2);
            if (ph == 0) store_raw(cfr0, cfr1, scrw, 128, q, tq);  // h still live as A
        }
        #pragma unroll
        for (int r = 0; r < 4; r++) {
            S[r]  += __shfl_xor_sync(0xffffffffu, S[r], 1);
            S[r]  += __shfl_xor_sync(0xffffffffu, S[r], 2);
            S2[r] += __shfl_xor_sync(0xffffffffu, S2[r], 1);
            S2[r] += __shfl_xor_sync(0xffffffffu, S2[r], 2);
            m[r] = S[r] * (1.0f / 256.0f);
            inv[r] = rsqrtf(S2[r] * (1.0f / 256.0f) - m[r] * m[r] + EPS_LN);
        }
        norm_reg(cfr0, cfr1, hw, 128, cb + 2*256, cb + 3*256, m, inv, q, tq);
        norm_mem(scrw, 128, hw, cb + 2*256, cb + 3*256, m, inv, q, tq);
        __syncwarp();

        // ===== L3: C = b3p; += h @ W3; x -= 0.1*C =====
        // pass0: cols 0..127
        init_bias2(cfr0, cfr1, cb + 5 * 256, 0, 8, q);
        gemm2<KT, 8>(cfr0, cfr1, hw, HS, g_W3_hi, g_W3_lo, NTP3, 0, lane);
        #pragma unroll
        for (int p = 0; p < 8; p++) {
            const float* a = cfr0 + p * 8;
            const float* b = cfr1 + p * 8;
            #pragma unroll
            for (int h = 0; h < 2; h++) {
                const int c = p * 16 + 8 * h + 2 * q;
                float2 v;
                v = *(float2*)(xw + tq * XS + c);
                v.x -= 0.1f * a[4*h+0]; v.y -= 0.1f * a[4*h+1];
                *(float2*)(xw + tq * XS + c) = v;
                v = *(float2*)(xw + (tq + 8) * XS + c);
                v.x -= 0.1f * a[4*h+2]; v.y -= 0.1f * a[4*h+3];
                *(float2*)(xw + (tq + 8) * XS + c) = v;
                v = *(float2*)(xw + (tq + 16) * XS + c);
                v.x -= 0.1f * b[4*h+0]; v.y -= 0.1f * b[4*h+1];
                *(float2*)(xw + (tq + 16) * XS + c) = v;
                v = *(float2*)(xw + (tq + 24) * XS + c);
                v.x -= 0.1f * b[4*h+2]; v.y -= 0.1f * b[4*h+3];
                *(float2*)(xw + (tq + 24) * XS + c) = v;
            }
        }
        // pass1: pair 8 -> cols 128..135 (subtile A only; B-subtile is all padding)
        init_bias2(cfr0, cfr1, cb + 5 * 256, 128, 1, q);
        gemm2<KT, 1>(cfr0, cfr1, hw, HS, g_W3_hi, g_W3_lo, NTP3, 8, lane);
        {
            const int c = 128 + 2 * q;
            float2 v;
            v = *(float2*)(xw + tq * XS + c);
            v.x -= 0.1f * cfr0[0]; v.y -= 0.1f * cfr0[1];
            *(float2*)(xw + tq * XS + c) = v;
            v = *(float2*)(xw + (tq + 8) * XS + c);
            v.x -= 0.1f * cfr0[2]; v.y -= 0.1f * cfr0[3];
            *(float2*)(xw + (tq + 8) * XS + c) = v;
            v = *(float2*)(xw + (tq + 16) * XS + c);
            v.x -= 0.1f * cfr1[0]; v.y -= 0.1f * cfr1[1];
            *(float2*)(xw + (tq + 16) * XS + c) = v;
            v = *(float2*)(xw + (tq + 24) * XS + c);
            v.x -= 0.1f * cfr1[2]; v.y -= 0.1f * cfr1[3];
            *(float2*)(xw + (tq + 24) * XS + c) = v;
        }
        __syncwarp();
    }

    // ---- epilogue: masked gumbel softmax argmax (straight-through) + tanh ----
    #pragma unroll 1
    for (int i = 0; i < WROWS; i++) {
        const size_t gr = grow0 + wr + i;
        const int c0 = lane * 4;
        const float4 xv = *(const float4*)(xw + i * XS + c0);
        const float4 mk = *(const float4*)(amask  + gr * 128 + c0);
        const float4 gn = *(const float4*)(gumbel + gr * 128 + c0);
        float z[4];
        z[0] = xv.x + (1.0f - mk.x) * (-1e9f) + gn.x;
        z[1] = xv.y + (1.0f - mk.y) * (-1e9f) + gn.y;
        z[2] = xv.z + (1.0f - mk.z) * (-1e9f) + gn.z;
        z[3] = xv.w + (1.0f - mk.w) * (-1e9f) + gn.w;
        float best = z[0]; int bi = c0;
        #pragma unroll
        for (int j = 1; j < 4; j++) if (z[j] > best) { best = z[j]; bi = c0 + j; }
        #pragma unroll
        for (int o = 16; o > 0; o >>= 1) {
            float ov = __shfl_xor_sync(0xffffffffu, best, o);
            int   oi = __shfl_xor_sync(0xffffffffu, bi,   o);
            if (ov > best || (ov == best && oi < bi)) { best = ov; bi = oi; }
        }
        float e[4]; float sl = 0.0f;
        #pragma unroll
        for (int j = 0; j < 4; j++) { e[j] = expf(z[j] - best); sl += e[j]; }
        #pragma unroll
        for (int o = 16; o > 0; o >>= 1) sl += __shfl_xor_sync(0xffffffffu, sl, o);
        #pragma unroll
        for (int j = 0; j < 4; j++) {
            const float p  = e[j] / sl;
            const float yh = (c0 + j == bi) ? 1.0f : 0.0f;
            const float tv = yh + p;
            out[gr * ADIM + c0 + j] = tv - p;
        }
        if (lane == 0) out[gr * ADIM + 128] = tanhf(xw[i * XS + 128]);
    }
}

extern "C" void kernel_launch(void* const* d_in, const int* in_sizes, int n_in,
                              void* d_out, int out_size)
{
    const float* state  = (const float*)d_in[0];
    const float* amask  = (const float*)d_in[1];
    const float* x_init = (const float*)d_in[2];
    const float* gumbel = (const float*)d_in[3];
    const float* W1     = (const float*)d_in[4];
    const float* b1     = (const float*)d_in[5];
    const float* g1     = (const float*)d_in[6];
    const float* be1    = (const float*)d_in[7];
    const float* W2     = (const float*)d_in[8];
    const float* b2     = (const float*)d_in[9];
    const float* g2     = (const float*)d_in[10];
    const float* be2    = (const float*)d_in[11];
    const float* W3     = (const float*)d_in[12];
    const float* b3     = (const float*)d_in[13];
    float* out          = (float*)d_out;

    pack_all<<<(R3 + 255) / 256, 256>>>(W1, W2, W3, b3);

    cudaFuncSetAttribute(actor_kernel,
                         cudaFuncAttributeMaxDynamicSharedMemorySize,
                         (int)SMEM_BYTES);

    actor_kernel<<<NROWS / TM, 128, SMEM_BYTES>>>(
        state, amask, x_init, gumbel,
        W1, b1, g1, be1, W2, b2, g2, be2, b3, out);
}

// round 17
// speedup vs baseline: 1.4607x; 1.4607x over previous
#include <cuda_runtime.h>
#include <cstdint>
#include <math.h>

// ---------------- problem constants ----------------
#define NROWS   65536
#define SDIM    256
#define ADIM    129
#define HID     256
#define NSTEP   30
#define EPS_LN  1e-5f

#define TM      64      // rows per CTA
#define WROWS   16      // rows per warp (m16 tiles)
#define NW      4
#define HS      260     // h smem stride (conflict-free scalar A reads)
#define XS      140     // x smem stride
#define NT      32      // n-tiles for N=256
#define NTP     16      // nt pairs
#define NT3     18      // n-tiles for W3 (N padded 129->144)
#define NTP3    9
#define KT      32      // k-tiles for K=256
#define KT1     17      // k-tiles for K=136 (x part, 129 padded)

typedef unsigned int u32;

__device__ __forceinline__ u32 cvt_tf32(float x) {
    u32 r; asm("cvt.rna.tf32.f32 %0, %1;" : "=r"(r) : "f"(x)); return r;
}
__device__ __forceinline__ void mma8(float* c, const u32 a[4], u32 b0, u32 b1) {
    asm("mma.sync.aligned.m16n8k8.row.col.f32.tf32.tf32.f32 "
        "{%0,%1,%2,%3},{%4,%5,%6,%7},{%8,%9},{%0,%1,%2,%3};"
        : "+f"(c[0]), "+f"(c[1]), "+f"(c[2]), "+f"(c[3])
        : "r"(a[0]), "r"(a[1]), "r"(a[2]), "r"(a[3]), "r"(b0), "r"(b1));
}

// ---------------- weight fragment streams (hi/lo tf32 split) ----------------
// +128 floats padding: prefetch reads one unit past the end
__device__ float g_W1s_hi[KT  * NTP  * 32 * 4 + 128];
__device__ float g_W1s_lo[KT  * NTP  * 32 * 4 + 128];
__device__ float g_W1x_hi[KT1 * NTP  * 32 * 4 + 128];
__device__ float g_W1x_lo[KT1 * NTP  * 32 * 4 + 128];
__device__ float g_W2_hi [KT  * NTP  * 32 * 4 + 128];
__device__ float g_W2_lo [KT  * NTP  * 32 * 4 + 128];
__device__ float g_W3_hi [KT  * NTP3 * 32 * 4 + 128];
__device__ float g_W3_lo [KT  * NTP3 * 32 * 4 + 128];
__device__ float g_b3p[NT3 * 8];
// per-warp-tile S1 fragments (thread-private roundtrip, frag order)
__device__ float g_S1f[(size_t)(NROWS / WROWS) * NT * 32 * 4];  // 64 MB

// one fragment slot (validK/validN guard, hi/lo split)
__device__ __forceinline__ void pack_region(const float* __restrict__ src,
                                            float* hi, float* lo, int stride,
                                            int validK, int validN, int ntpn,
                                            int kOff, int idx)
{
    int lane = idx & 31, rest = idx >> 5;
    int p = rest % ntpn, kt = rest / ntpn;
    int q = lane & 3, tq = lane >> 2;
    int k0 = kt * 8 + q, k1 = k0 + 4;
    int c0 = (2 * p) * 8 + tq, c1 = (2 * p + 1) * 8 + tq;
    float v[4];
    v[0] = (k0 < validK && c0 < validN) ? src[(size_t)(k0 + kOff) * stride + c0] : 0.0f;
    v[1] = (k1 < validK && c0 < validN) ? src[(size_t)(k1 + kOff) * stride + c0] : 0.0f;
    v[2] = (k0 < validK && c1 < validN) ? src[(size_t)(k0 + kOff) * stride + c1] : 0.0f;
    v[3] = (k1 < validK && c1 < validN) ? src[(size_t)(k1 + kOff) * stride + c1] : 0.0f;
    float4 Hv, Lv;
    u32 h;
    h = cvt_tf32(v[0]); Hv.x = __uint_as_float(h); Lv.x = __uint_as_float(cvt_tf32(v[0] - __uint_as_float(h)));
    h = cvt_tf32(v[1]); Hv.y = __uint_as_float(h); Lv.y = __uint_as_float(cvt_tf32(v[1] - __uint_as_float(h)));
    h = cvt_tf32(v[2]); Hv.z = __uint_as_float(h); Lv.z = __uint_as_float(cvt_tf32(v[2] - __uint_as_float(h)));
    h = cvt_tf32(v[3]); Hv.w = __uint_as_float(h); Lv.w = __uint_as_float(cvt_tf32(v[3] - __uint_as_float(h)));
    ((float4*)hi)[idx] = Hv;
    ((float4*)lo)[idx] = Lv;
}

// ONE pack kernel (so ncu -s 5 lands on actor_kernel); also zeroes pad tails
#define R0 (KT  * NTP  * 32)
#define R1 (R0 + KT1 * NTP * 32)
#define R2 (R1 + KT  * NTP * 32)
#define R3 (R2 + KT  * NTP3 * 32)
__global__ void pack_all(const float* __restrict__ W1, const float* __restrict__ W2,
                         const float* __restrict__ W3, const float* __restrict__ b3)
{
    int i = blockIdx.x * 256 + threadIdx.x;
    if (i < 144) g_b3p[i] = (i < ADIM) ? b3[i] : 0.0f;
    if (i < 128) {   // zero the prefetch pads
        g_W1s_hi[R0 * 4 + i] = 0.0f; g_W1s_lo[R0 * 4 + i] = 0.0f;
        g_W1x_hi[(R1 - R0) * 4 + i] = 0.0f; g_W1x_lo[(R1 - R0) * 4 + i] = 0.0f;
        g_W2_hi[(R2 - R1) * 4 + i] = 0.0f;  g_W2_lo[(R2 - R1) * 4 + i] = 0.0f;
        g_W3_hi[(R3 - R2) * 4 + i] = 0.0f;  g_W3_lo[(R3 - R2) * 4 + i] = 0.0f;
    }
    if (i < R0)      pack_region(W1, g_W1s_hi, g_W1s_lo, HID, 256, 256, NTP, 0, i);
    else if (i < R1) pack_region(W1, g_W1x_hi, g_W1x_lo, HID, 129, 256, NTP, SDIM, i - R0);
    else if (i < R2) pack_region(W2, g_W2_hi,  g_W2_lo,  HID, 256, 256, NTP, 0, i - R1);
    else if (i < R3) pack_region(W3, g_W3_hi,  g_W3_lo,  ADIM, 256, 129, NTP3, 0, i - R2);
}

// ---------------- core GEMM: C[M16 x N] += A @ B (3xTF32), B double-buffered ----------------
template<int KTN, int NTPN>
__device__ __forceinline__ void gemm_frag(float* cfr, const float* __restrict__ A,
                                          int astr, const float* __restrict__ Bh,
                                          const float* __restrict__ Bl, int lane)
{
    const int q = lane & 3, tq = lane >> 2;
    const float4* bh = (const float4*)Bh + lane;
    const float4* bl = (const float4*)Bl + lane;
    float4 hc = bh[0];
    float4 lc = bl[0];
    #pragma unroll 1
    for (int kt = 0; kt < KTN; kt++) {
        const int k0 = kt * 8 + q;
        const float a0 = A[tq * astr + k0];
        const float a1 = A[(tq + 8) * astr + k0];
        const float a2 = A[tq * astr + k0 + 4];
        const float a3 = A[(tq + 8) * astr + k0 + 4];
        u32 ah[4], al[4];
        ah[0] = cvt_tf32(a0); al[0] = cvt_tf32(a0 - __uint_as_float(ah[0]));
        ah[1] = cvt_tf32(a1); al[1] = cvt_tf32(a1 - __uint_as_float(ah[1]));
        ah[2] = cvt_tf32(a2); al[2] = cvt_tf32(a2 - __uint_as_float(ah[2]));
        ah[3] = cvt_tf32(a3); al[3] = cvt_tf32(a3 - __uint_as_float(ah[3]));
        #pragma unroll
        for (int p = 0; p < NTPN; p++) {
            // prefetch next unit (stream is contiguous in (kt,p); +128f pad covers tail)
            const float4 hn = bh[(kt * NTPN + p + 1) * 32];
            const float4 ln = bl[(kt * NTPN + p + 1) * 32];
            float* cc = cfr + p * 8;
            const u32 h0 = __float_as_uint(hc.x), h1 = __float_as_uint(hc.y);
            const u32 h2 = __float_as_uint(hc.z), h3 = __float_as_uint(hc.w);
            const u32 l0 = __float_as_uint(lc.x), l1 = __float_as_uint(lc.y);
            const u32 l2 = __float_as_uint(lc.z), l3 = __float_as_uint(lc.w);
            mma8(cc,     ah, h0, h1);
            mma8(cc,     ah, l0, l1);
            mma8(cc,     al, h0, h1);
            mma8(cc + 4, ah, h2, h3);
            mma8(cc + 4, ah, l2, l3);
            mma8(cc + 4, al, h2, h3);
            hc = hn; lc = ln;
        }
    }
}

// ---------------- LayerNorm + ReLU on C fragments -> h smem ----------------
__device__ __forceinline__ void ln_relu_frag(const float* cfr, float* __restrict__ hw,
                                             const float* __restrict__ g,
                                             const float* __restrict__ be, int lane)
{
    const int q = lane & 3, tq = lane >> 2;
    float s0 = 0.0f, s1 = 0.0f;
    #pragma unroll
    for (int nt = 0; nt < NT; nt++) {
        s0 += cfr[4 * nt] + cfr[4 * nt + 1];
        s1 += cfr[4 * nt + 2] + cfr[4 * nt + 3];
    }
    s0 += __shfl_xor_sync(0xffffffffu, s0, 1); s0 += __shfl_xor_sync(0xffffffffu, s0, 2);
    s1 += __shfl_xor_sync(0xffffffffu, s1, 1); s1 += __shfl_xor_sync(0xffffffffu, s1, 2);
    const float m0 = s0 * (1.0f / 256.0f), m1 = s1 * (1.0f / 256.0f);
    float v0 = 0.0f, v1 = 0.0f;
    #pragma unroll
    for (int nt = 0; nt < NT; nt++) {
        float d0 = cfr[4 * nt] - m0,     d1 = cfr[4 * nt + 1] - m0;
        float d2 = cfr[4 * nt + 2] - m1, d3 = cfr[4 * nt + 3] - m1;
        v0 += d0 * d0 + d1 * d1;
        v1 += d2 * d2 + d3 * d3;
    }
    v0 += __shfl_xor_sync(0xffffffffu, v0, 1); v0 += __shfl_xor_sync(0xffffffffu, v0, 2);
    v1 += __shfl_xor_sync(0xffffffffu, v1, 1); v1 += __shfl_xor_sync(0xffffffffu, v1, 2);
    const float i0 = rsqrtf(v0 * (1.0f / 256.0f) + EPS_LN);
    const float i1 = rsqrtf(v1 * (1.0f / 256.0f) + EPS_LN);
    #pragma unroll
    for (int nt = 0; nt < NT; nt++) {
        const int col = nt * 8 + 2 * q;
        const float2 gg = *(const float2*)(g + col);
        const float2 bb = *(const float2*)(be + col);
        float2 ha, hb2;
        ha.x  = fmaxf(fmaf((cfr[4 * nt]     - m0) * i0, gg.x, bb.x), 0.0f);
        ha.y  = fmaxf(fmaf((cfr[4 * nt + 1] - m0) * i0, gg.y, bb.y), 0.0f);
        hb2.x = fmaxf(fmaf((cfr[4 * nt + 2] - m1) * i1, gg.x, bb.x), 0.0f);
        hb2.y = fmaxf(fmaf((cfr[4 * nt + 3] - m1) * i1, gg.y, bb.y), 0.0f);
        *(float2*)(hw + tq * HS + col)       = ha;
        *(float2*)(hw + (tq + 8) * HS + col) = hb2;
    }
}

// smem: consts 8*256 + h 64*260 + x 64*140 = 27648 floats = 110592 B -> 2 CTAs/SM
#define CBF   (8 * 256)
#define HBF   (TM * HS)
#define XBF   (TM * XS)
#define SMEM_BYTES ((CBF + HBF + XBF) * sizeof(float))

__global__ void __launch_bounds__(128, 2)
actor_kernel(const float* __restrict__ state,  const float* __restrict__ amask,
             const float* __restrict__ x_init, const float* __restrict__ gumbel,
             const float* __restrict__ W1,     const float* __restrict__ b1,
             const float* __restrict__ g1,     const float* __restrict__ be1,
             const float* __restrict__ W2,     const float* __restrict__ b2,
             const float* __restrict__ g2,     const float* __restrict__ be2,
             const float* __restrict__ b3,     float* __restrict__ out)
{
    extern __shared__ float sm[];
    float* cb = sm;               // [8][256]: g1,be1,g2,be2,b2,b3p,w385,b1
    float* hb = sm + CBF;         // [64][260]
    float* xb = sm + CBF + HBF;   // [64][140]

    const int tid  = threadIdx.x;
    const int lane = tid & 31;
    const int wid  = tid >> 5;
    const int q    = lane & 3, tq = lane >> 2;
    const int wr   = wid * WROWS;
    const size_t grow0 = (size_t)blockIdx.x * TM;
    float* hw = hb + wr * HS;
    float* xw = xb + wr * XS;
    const int warpgid = blockIdx.x * NW + wid;
    float* s1p = g_S1f + (size_t)warpgid * (NT * 32 * 4);

    // ---- stage per-layer constants into smem ----
    for (int i = tid; i < 256; i += 128) {
        cb[0 * 256 + i] = g1[i];
        cb[1 * 256 + i] = be1[i];
        cb[2 * 256 + i] = g2[i];
        cb[3 * 256 + i] = be2[i];
        cb[4 * 256 + i] = b2[i];
        cb[5 * 256 + i] = (i < NT3 * 8) ? g_b3p[i] : 0.0f;
        cb[6 * 256 + i] = W1[(size_t)385 * HID + i];
        cb[7 * 256 + i] = b1[i];
    }
    __syncthreads();

    // ---- stage x rows (stride 129) and state rows (each warp its 16 rows) ----
    #pragma unroll 1
    for (int i = 0; i < WROWS; i++) {
        const size_t gr = grow0 + wr + i;
        const float* xp = x_init + gr * ADIM;
        #pragma unroll
        for (int j = 0; j < 4; j++) xw[i * XS + lane + 32 * j] = xp[lane + 32 * j];
        if (lane == 0) xw[i * XS + 128] = xp[128];
        if (lane >= 1 && lane <= 11) xw[i * XS + 128 + lane] = 0.0f;
        const float* sp = state + gr * SDIM;
        *(float4*)(hw + i * HS + lane * 4)       = *(const float4*)(sp + lane * 4);
        *(float4*)(hw + i * HS + 128 + lane * 4) = *(const float4*)(sp + 128 + lane * 4);
    }
    __syncwarp();

    float cfr[NT * 4];   // C fragments: [nt]{c0,c1,c2,c3}

    // ---- S1 = state @ W1[0:256] + b1 -> g_S1f (frag order, thread-private) ----
    #pragma unroll
    for (int nt = 0; nt < NT; nt++) {
        const float2 bb = *(const float2*)(cb + 7 * 256 + nt * 8 + 2 * q);
        cfr[4 * nt] = bb.x; cfr[4 * nt + 1] = bb.y;
        cfr[4 * nt + 2] = bb.x; cfr[4 * nt + 3] = bb.y;
    }
    gemm_frag<KT, NTP>(cfr, hw, HS, g_W1s_hi, g_W1s_lo, lane);
    #pragma unroll
    for (int nt = 0; nt < NT; nt++) {
        float4 v; v.x = cfr[4 * nt]; v.y = cfr[4 * nt + 1];
        v.z = cfr[4 * nt + 2]; v.w = cfr[4 * nt + 3];
        *(float4*)(s1p + nt * 128 + lane * 4) = v;
    }
    __syncwarp();

    // ---- 30 diffusion steps (warps fully independent) ----
    #pragma unroll 1
    for (int s = 0; s < NSTEP; s++) {
        const float t = (float)(NSTEP - 1 - s);

        // L1: C = S1 + t*w385; += x @ W1x; LN+ReLU -> h
        #pragma unroll
        for (int nt = 0; nt < NT; nt++) {
            const float4 sv = *(const float4*)(s1p + nt * 128 + lane * 4);
            const float2 wv = *(const float2*)(cb + 6 * 256 + nt * 8 + 2 * q);
            cfr[4 * nt]     = fmaf(t, wv.x, sv.x);
            cfr[4 * nt + 1] = fmaf(t, wv.y, sv.y);
            cfr[4 * nt + 2] = fmaf(t, wv.x, sv.z);
            cfr[4 * nt + 3] = fmaf(t, wv.y, sv.w);
        }
        gemm_frag<KT1, NTP>(cfr, xw, XS, g_W1x_hi, g_W1x_lo, lane);
        __syncwarp();
        ln_relu_frag(cfr, hw, cb + 0 * 256, cb + 1 * 256, lane);
        __syncwarp();

        // L2: C = b2; += h @ W2; LN+ReLU -> h
        #pragma unroll
        for (int nt = 0; nt < NT; nt++) {
            const float2 bb = *(const float2*)(cb + 4 * 256 + nt * 8 + 2 * q);
            cfr[4 * nt] = bb.x; cfr[4 * nt + 1] = bb.y;
            cfr[4 * nt + 2] = bb.x; cfr[4 * nt + 3] = bb.y;
        }
        gemm_frag<KT, NTP>(cfr, hw, HS, g_W2_hi, g_W2_lo, lane);
        __syncwarp();
        ln_relu_frag(cfr, hw, cb + 2 * 256, cb + 3 * 256, lane);
        __syncwarp();

        // L3: C = b3p; += h @ W3; x -= 0.1*C
        #pragma unroll
        for (int nt = 0; nt < NT3; nt++) {
            const float2 bb = *(const float2*)(cb + 5 * 256 + nt * 8 + 2 * q);
            cfr[4 * nt] = bb.x; cfr[4 * nt + 1] = bb.y;
            cfr[4 * nt + 2] = bb.x; cfr[4 * nt + 3] = bb.y;
        }
        gemm_frag<KT, NTP3>(cfr, hw, HS, g_W3_hi, g_W3_lo, lane);
        __syncwarp();
        #pragma unroll
        for (int nt = 0; nt < 17; nt++) {      // cols 0..135 (x buffer has 140)
            const int col = nt * 8 + 2 * q;
            xw[tq * XS + col]           -= 0.1f * cfr[4 * nt];
            xw[tq * XS + col + 1]       -= 0.1f * cfr[4 * nt + 1];
            xw[(tq + 8) * XS + col]     -= 0.1f * cfr[4 * nt + 2];
            xw[(tq + 8) * XS + col + 1] -= 0.1f * cfr[4 * nt + 3];
        }
        __syncwarp();
    }

    // ---- epilogue: masked gumbel softmax argmax (straight-through) + tanh ----
    #pragma unroll 1
    for (int i = 0; i < WROWS; i++) {
        const size_t gr = grow0 + wr + i;
        const int c0 = lane * 4;
        const float4 xv = *(const float4*)(xw + i * XS + c0);
        const float4 mk = *(const float4*)(amask  + gr * 128 + c0);
        const float4 gn = *(const float4*)(gumbel + gr * 128 + c0);
        float z[4];
        z[0] = xv.x + (1.0f - mk.x) * (-1e9f) + gn.x;
        z[1] = xv.y + (1.0f - mk.y) * (-1e9f) + gn.y;
        z[2] = xv.z + (1.0f - mk.z) * (-1e9f) + gn.z;
        z[3] = xv.w + (1.0f - mk.w) * (-1e9f) + gn.w;
        float best = z[0]; int bi = c0;
        #pragma unroll
        for (int j = 1; j < 4; j++) if (z[j] > best) { best = z[j]; bi = c0 + j; }
        #pragma unroll
        for (int o = 16; o > 0; o >>= 1) {
            float ov = __shfl_xor_sync(0xffffffffu, best, o);
            int   oi = __shfl_xor_sync(0xffffffffu, bi,   o);
            if (ov > best || (ov == best && oi < bi)) { best = ov; bi = oi; }
        }
        float e[4]; float sl = 0.0f;
        #pragma unroll
        for (int j = 0; j < 4; j++) { e[j] = expf(z[j] - best); sl += e[j]; }
        #pragma unroll
        for (int o = 16; o > 0; o >>= 1) sl += __shfl_xor_sync(0xffffffffu, sl, o);
        #pragma unroll
        for (int j = 0; j < 4; j++) {
            const float p  = e[j] / sl;
            const float yh = (c0 + j == bi) ? 1.0f : 0.0f;
            const float tv = yh + p;
            out[gr * ADIM + c0 + j] = tv - p;
        }
        if (lane == 0) out[gr * ADIM + 128] = tanhf(xw[i * XS + 128]);
    }
}

extern "C" void kernel_launch(void* const* d_in, const int* in_sizes, int n_in,
                              void* d_out, int out_size)
{
    const float* state  = (const float*)d_in[0];
    const float* amask  = (const float*)d_in[1];
    const float* x_init = (const float*)d_in[2];
    const float* gumbel = (const float*)d_in[3];
    const float* W1     = (const float*)d_in[4];
    const float* b1     = (const float*)d_in[5];
    const float* g1     = (const float*)d_in[6];
    const float* be1    = (const float*)d_in[7];
    const float* W2     = (const float*)d_in[8];
    const float* b2     = (const float*)d_in[9];
    const float* g2     = (const float*)d_in[10];
    const float* be2    = (const float*)d_in[11];
    const float* W3     = (const float*)d_in[12];
    const float* b3     = (const float*)d_in[13];
    float* out          = (float*)d_out;

    pack_all<<<(R3 + 255) / 256, 256>>>(W1, W2, W3, b3);

    cudaFuncSetAttribute(actor_kernel,
                         cudaFuncAttributeMaxDynamicSharedMemorySize,
                         (int)SMEM_BYTES);

    actor_kernel<<<NROWS / TM, 128, SMEM_BYTES>>>(
        state, amask, x_init, gumbel,
        W1, b1, g1, be1, W2, b2, g2, be2, b3, out);
}